// round 11
// baseline (speedup 1.0000x reference)
#include <cuda_runtime.h>
#include <cstdint>
#include <math.h>

#define B_   16
#define T_   512
#define P_   2048
#define SN   256
#define SD   1024
#define NC_DEN 128
#define NC_NUM 16
#define NCTA (NC_DEN + NC_NUM)
#define NTHR 256

// -------------------- persistent device scratch (no runtime allocation) -----
__device__ float g_qden[2][SD * 16];
__device__ float g_qnum[2][SN * 16];
__device__ float g_part[NCTA][16];
__device__ double g_lp[2][16];
__device__ unsigned long long g_bar;   // monotonic; survives graph replays

// -------------------- grid barrier (all CTAs co-resident: 144 <= 148 SMs) ---
__device__ __forceinline__ void grid_barrier() {
    __syncthreads();
    if (threadIdx.x == 0) {
        __threadfence();
        unsigned long long old = atomicAdd(&g_bar, 1ULL);
        unsigned long long target = (old / NCTA + 1ULL) * (unsigned long long)NCTA;
        volatile unsigned long long* vb = &g_bar;
        while (*vb < target) { __nanosleep(32); }
        __threadfence();
    }
    __syncthreads();
}

// -------------------- one FSM (num or den), one column tile per CTA ---------
// q layout in global: q[i*16 + b]  (b contiguous -> coalesced load, LDS.128 in GEMM)
template <int S, int JT, int PROB>
__device__ void run_fsm(const float* __restrict__ input,
                        const int*   __restrict__ seqlen,
                        const float* __restrict__ initv,
                        const float* __restrict__ trans,
                        const float* __restrict__ finalv,
                        const int*   __restrict__ pdf,
                        float* q0buf, float* q1buf,
                        int tileIdx, bool tracker, int ctaFirst, int nCtaProb)
{
    constexpr int NSEG = NTHR / (4 * JT);   // den: 8, num: 4
    constexpr int ILEN = S / NSEG;          // den: 128, num: 64
    constexpr int NOUT = 16 * JT;           // den: 128, num: 256
    constexpr int CH   = S / 16;            // den: 64, num: 16

    const int tid = threadIdx.x;
    const int jbase = tileIdx * JT;

    extern __shared__ float sm[];
    float* Es     = sm;               // up to 8192 floats  (S*JT)
    float* qs     = sm + 8192;        // up to 16384 floats (S*16)
    float* red    = qs + 16384;       // 1024 floats
    float* ssum   = red + 1024;       // 256 floats
    float* sm_s   = ssum + 256;       // 16
    float* sm_inv = sm_s + 16;        // 16
    int*   sm_len = (int*)(sm_inv + 16); // 16 ints

    if (tid < 16) sm_len[tid] = seqlen[tid];

    // E tile resident in SMEM for all steps: Es[i*JT + jl] = exp(trans[i][jbase+jl])
    for (int k = tid; k < S * JT; k += NTHR) {
        int i = k / JT, jl = k % JT;
        Es[k] = expf(__ldg(&trans[(size_t)i * S + jbase + jl]));
    }

    // per-output registers
    int b = 0, jg = 0, pdfj = 0;
    float qlast = 0.f;
    if (tid < NOUT) {
        b = tid / JT;
        int jl = tid % JT;
        jg = jbase + jl;
        pdfj = __ldg(&pdf[jg]);
        float a0 = __ldg(&initv[jg]) + __ldg(&input[(size_t)b * T_ * P_ + pdfj]);
        qlast = expf(a0);                         // C_b starts at 0
        __stcg(&q0buf[(size_t)jg * 16 + b], qlast);
    }

    double Creg = 0.0;                            // tracker-only running log-offset

    const int j_lds = tid % JT;
    const int bq    = (tid / JT) & 3;
    const int iseg  = tid / (4 * JT);
    const int i0    = iseg * ILEN;

    for (int t = 1; t < T_; ++t) {
        grid_barrier();                           // q(t-1) globally visible
        const float* qprev = (t & 1) ? q0buf : q1buf;
        float*       qcur  = (t & 1) ? q1buf : q0buf;

        // prefetch this step's emission (hidden under GEMM)
        float ev = 0.f;
        if (tid < NOUT) ev = __ldg(&input[((size_t)b * T_ + t) * P_ + pdfj]);

        // stage q(t-1) into SMEM (L2-coherent loads; writers were other SMs)
        {
            const float4* src = (const float4*)qprev;
            float4*       dst = (float4*)qs;
            #pragma unroll
            for (int k = tid; k < S * 4; k += NTHR) dst[k] = __ldcg(src + k);
        }
        __syncthreads();

        // s_b = sum_i q(t-1)[b,i]  (deterministic, identical across all CTAs)
        {
            int bb = tid & 15, ch = tid >> 4;
            float p = 0.f;
            const float* qp = qs + (ch * CH) * 16 + bb;
            #pragma unroll 4
            for (int x = 0; x < CH; x++) p += qp[x * 16];
            ssum[tid] = p;
        }
        __syncthreads();
        if (tid < 16) {
            float s = 0.f;
            #pragma unroll
            for (int c = 0; c < 16; c++) s += ssum[c * 16 + tid];
            sm_s[tid]   = s;
            sm_inv[tid] = 1.0f / s;
            if (tracker && t < sm_len[tid]) Creg += log((double)s);
        }
        __syncthreads();

        // GEMM slice: dot[b, j_lds] over i in [i0, i0+ILEN), 4 b's per thread
        float a0 = 0.f, a1 = 0.f, a2 = 0.f, a3 = 0.f;
        {
            const float4* q4 = (const float4*)qs;
            #pragma unroll 8
            for (int ii = 0; ii < ILEN; ii++) {
                int i = i0 + ii;
                float  e  = Es[i * JT + j_lds];
                float4 qv = q4[i * 4 + bq];
                a0 = fmaf(qv.x, e, a0);
                a1 = fmaf(qv.y, e, a1);
                a2 = fmaf(qv.z, e, a2);
                a3 = fmaf(qv.w, e, a3);
            }
        }
        {
            int ob = bq * 4;
            red[((ob + 0) * JT + j_lds) * NSEG + iseg] = a0;
            red[((ob + 1) * JT + j_lds) * NSEG + iseg] = a1;
            red[((ob + 2) * JT + j_lds) * NSEG + iseg] = a2;
            red[((ob + 3) * JT + j_lds) * NSEG + iseg] = a3;
        }
        __syncthreads();

        // q(t)[b,j] = dot/s_b * exp(emis)  (frozen b: carry forward)
        if (tid < NOUT) {
            float dot = 0.f;
            #pragma unroll
            for (int s2 = 0; s2 < NSEG; s2++) dot += red[tid * NSEG + s2];
            float qn;
            if (t < sm_len[b]) qn = dot * sm_inv[b] * expf(ev);
            else               qn = qs[jg * 16 + b];
            qlast = qn;
            __stcg(&qcur[(size_t)jg * 16 + b], qn);
        }
    }

    // ---------------- final: logprob_b = C_b + log( sum_j q_T[b,j]*exp(final_j) )
    __syncthreads();
    if (tid < NOUT) red[tid] = qlast * expf(__ldg(&finalv[jg]));
    __syncthreads();
    if (tid < 16) {
        float p = 0.f;
        #pragma unroll
        for (int c = 0; c < JT; c++) p += red[tid * JT + c];
        g_part[blockIdx.x][tid] = p;
    }
    __threadfence();
    grid_barrier();
    if (tracker && tid < 16) {
        double tot = 0.0;
        for (int c = 0; c < nCtaProb; c++)
            tot += (double)__ldcg(&g_part[ctaFirst + c][tid]);
        g_lp[PROB][tid] = Creg + log(tot);
    }
    __threadfence();
    grid_barrier();
}

// -------------------- kernel ------------------------------------------------
__global__ void __launch_bounds__(NTHR, 1)
lfmmi_kernel(const float* input, const int* seqlen,
             const float* n_init, const float* n_trans, const float* n_final, const int* n_pdf,
             const float* d_init, const float* d_trans, const float* d_final, const int* d_pdf,
             float* out)
{
    int cta = blockIdx.x;
    if (cta < NC_DEN) {
        run_fsm<SD, 8, 0>(input, seqlen, d_init, d_trans, d_final, d_pdf,
                          g_qden[0], g_qden[1], cta, cta == 0, 0, NC_DEN);
    } else {
        run_fsm<SN, 16, 1>(input, seqlen, n_init, n_trans, n_final, n_pdf,
                           g_qnum[0], g_qnum[1], cta - NC_DEN, cta == NC_DEN,
                           NC_DEN, NC_NUM);
    }
    if (cta == 0 && threadIdx.x == 0) {
        double dsum = 0.0, nsum = 0.0;
        for (int bb = 0; bb < 16; ++bb) {
            dsum += __ldcg(&g_lp[0][bb]);
            nsum += __ldcg(&g_lp[1][bb]);
        }
        out[0] = (float)(-(nsum - dsum));
    }
}

// -------------------- launch -------------------------------------------------
extern "C" void kernel_launch(void* const* d_in, const int* in_sizes, int n_in,
                              void* d_out, int out_size)
{
    (void)in_sizes; (void)n_in; (void)out_size;
    const size_t smem = 25904 * sizeof(float);   // 103,616 B
    cudaFuncSetAttribute(lfmmi_kernel,
                         cudaFuncAttributeMaxDynamicSharedMemorySize, (int)smem);
    lfmmi_kernel<<<NCTA, NTHR, smem>>>(
        (const float*)d_in[0], (const int*)d_in[1],
        (const float*)d_in[2], (const float*)d_in[3], (const float*)d_in[4], (const int*)d_in[5],
        (const float*)d_in[6], (const float*)d_in[7], (const float*)d_in[8], (const int*)d_in[9],
        (float*)d_out);
}

// round 12
// speedup vs baseline: 1.4225x; 1.4225x over previous
#include <cuda_runtime.h>
#include <cstdint>
#include <math.h>

#define B_   16
#define T_   512
#define P_   2048
#define SN   256
#define SD   1024
#define NC_DEN 128
#define NC_NUM 8
#define NCTA (NC_DEN + NC_NUM)
#define NTHR 512

// -------------------- persistent device scratch (no runtime allocation) -----
__device__ float g_qden[2][SD * 16];
__device__ float g_qnum[2][SN * 16];
__device__ float g_part[NCTA][16];
__device__ double g_lp[2][16];
__device__ unsigned long long g_bar;   // monotonic; survives graph replays

// -------------------- grid barrier (136 CTAs co-resident on 148+ SMs) -------
__device__ __forceinline__ void grid_barrier() {
    __syncthreads();
    if (threadIdx.x == 0) {
        __threadfence();
        unsigned long long old = atomicAdd(&g_bar, 1ULL);
        unsigned long long target = (old / NCTA + 1ULL) * (unsigned long long)NCTA;
        volatile unsigned long long* vb = &g_bar;
        while (*vb < target) { }
        __threadfence();
    }
    __syncthreads();
}

__device__ __forceinline__ void f4fma(float4& a, const float4& q, float e) {
    a.x = fmaf(q.x, e, a.x);
    a.y = fmaf(q.y, e, a.y);
    a.z = fmaf(q.z, e, a.z);
    a.w = fmaf(q.w, e, a.w);
}

// -------------------- one FSM (num or den), one column tile per CTA ---------
// q layout in global: q[i*16 + b]  (b contiguous)
template <int S, int JT, int PROB>
__device__ void run_fsm(const float* __restrict__ input,
                        const int*   __restrict__ seqlen,
                        const float* __restrict__ initv,
                        const float* __restrict__ trans,
                        const float* __restrict__ finalv,
                        const int*   __restrict__ pdf,
                        float* q0buf, float* q1buf,
                        int tileIdx, bool tracker, int ctaFirst, int nCtaProb)
{
    constexpr int JQ   = JT / 4;            // den: 2, num: 8
    constexpr int GRP  = 4 * JQ;            // threads per i-slice (den 8, num 32)
    constexpr int NSEG = NTHR / GRP;        // den: 64, num: 16
    constexpr int ILEN = S / NSEG;          // 16 (both)
    constexpr int NOUT = 16 * JT;           // den: 128, num: 512
    constexpr int ROWP = NOUT + 32;         // padded red row (bank-skew room)
    constexpr int NLD  = (S * 4) / NTHR;    // float4 stage loads/thread (den 8, num 2)

    const int tid   = threadIdx.x;
    const int lane  = tid & 31;
    const int warp  = tid >> 5;
    const int jbase = tileIdx * JT;

    extern __shared__ float sm[];
    float* Es     = sm;                       // 8192 floats (S*JT: 8192 both)
    float* qs     = sm + 8192;                // up to 16384 floats (S*16)
    float* red    = qs + 16384;               // up to 10240 floats (NSEG*ROWP)
    float* sswarp = red + 10240;              // 256 floats (16 warps x 16 b)
    float* sm_inv = sswarp + 256;             // 16
    int*   sm_len = (int*)(sm_inv + 16);      // 16 ints

    if (tid < 16) sm_len[tid] = seqlen[tid];

    // E tile resident in SMEM: Es[i*JT + jl] = exp(trans[i][jbase+jl])
    for (int k = tid; k < S * JT; k += NTHR) {
        int i = k / JT, jl = k % JT;
        Es[k] = expf(__ldg(&trans[(size_t)i * S + jbase + jl]));
    }

    // output-thread mapping: tid -> (b = tid%16, j = tid/16); global addr = jbase*16 + tid (coalesced)
    int b = 0, jg = 0, pdfj = 0;
    float qlast = 0.f;
    if (tid < NOUT) {
        b  = tid & 15;
        jg = jbase + (tid >> 4);
        pdfj = __ldg(&pdf[jg]);
        qlast = expf(__ldg(&initv[jg]) + __ldg(&input[(size_t)b * T_ * P_ + pdfj]));
        __stcg(&q0buf[(size_t)jbase * 16 + tid], qlast);
    }

    double Creg = 0.0;                        // tracker-only running log-offset

    // GEMM thread coords: 4b x 4j register tile
    const int jq   = tid % JQ;
    const int bq   = (tid / JQ) & 3;
    const int iseg = tid / GRP;
    const int i0   = iseg * ILEN;
    // red write base: out = (bq*4+cc)*JT + jq*4 (+jj), skew 8*bq
    float* wrbase = red + iseg * ROWP + bq * (4 * JT) + jq * 4 + bq * 8;
    // red read idx for output threads
    const int ridx = b * JT + (tid >> 4) + (b >> 2) * 8;

    for (int t = 1; t < T_; ++t) {
        grid_barrier();                       // q(t-1) globally visible
        const float* qprev = (t & 1) ? q0buf : q1buf;
        float*       qcur  = (t & 1) ? q1buf : q0buf;

        // prefetch this step's emission (used at the very end of the step)
        float ev = 0.f;
        if (tid < NOUT) ev = __ldg(&input[((size_t)b * T_ + t) * P_ + pdfj]);

        // stage q(t-1) into SMEM, fusing the per-b partial sum
        float4 ps = make_float4(0.f, 0.f, 0.f, 0.f);
        {
            const float4* src = (const float4*)qprev;
            float4*       dst = (float4*)qs;
            #pragma unroll
            for (int u = 0; u < NLD; u++) {
                int k = tid + u * NTHR;
                float4 v = __ldcg(src + k);
                dst[k] = v;
                ps.x += v.x; ps.y += v.y; ps.z += v.z; ps.w += v.w;
            }
        }
        // butterfly over lanes with same lane%4 (b-quad preserved)
        #pragma unroll
        for (int m = 4; m < 32; m <<= 1) {
            ps.x += __shfl_xor_sync(0xffffffffu, ps.x, m);
            ps.y += __shfl_xor_sync(0xffffffffu, ps.y, m);
            ps.z += __shfl_xor_sync(0xffffffffu, ps.z, m);
            ps.w += __shfl_xor_sync(0xffffffffu, ps.w, m);
        }
        if (lane < 4) ((float4*)sswarp)[warp * 4 + lane] = ps;   // sswarp[warp][b]
        __syncthreads();

        // warp 0 finalizes s while everyone else proceeds into the GEMM
        if (tid < 16) {
            float s = 0.f;
            #pragma unroll
            for (int w = 0; w < 16; w++) s += sswarp[w * 16 + tid];
            sm_inv[tid] = 1.0f / s;
            if (tracker && t < sm_len[tid]) Creg += (double)logf(s);
        }

        // GEMM slice: 16 accumulators (4 j x 4 b), ILEN=16 i's
        float4 a0 = make_float4(0,0,0,0), a1 = a0, a2 = a0, a3 = a0;
        {
            const float4* q4 = (const float4*)qs;
            const float4* E4 = (const float4*)Es;
            #pragma unroll
            for (int ii = 0; ii < ILEN; ii++) {
                int i = i0 + ii;
                float4 qv = q4[i * 4 + bq];
                float4 e4 = E4[i * JQ + jq];
                f4fma(a0, qv, e4.x);
                f4fma(a1, qv, e4.y);
                f4fma(a2, qv, e4.z);
                f4fma(a3, qv, e4.w);
            }
        }
        // transpose 4x4 (jj-major -> b-major components) and store float4-over-j
        {
            float4 t0 = make_float4(a0.x, a1.x, a2.x, a3.x);
            float4 t1 = make_float4(a0.y, a1.y, a2.y, a3.y);
            float4 t2 = make_float4(a0.z, a1.z, a2.z, a3.z);
            float4 t3 = make_float4(a0.w, a1.w, a2.w, a3.w);
            *(float4*)(wrbase + 0 * JT) = t0;
            *(float4*)(wrbase + 1 * JT) = t1;
            *(float4*)(wrbase + 2 * JT) = t2;
            *(float4*)(wrbase + 3 * JT) = t3;
        }
        __syncthreads();

        // q(t)[b,j] = dot / s_b * exp(emis); frozen b carries forward
        if (tid < NOUT) {
            float dot = 0.f;
            #pragma unroll
            for (int s2 = 0; s2 < NSEG; s2++) dot += red[s2 * ROWP + ridx];
            float qn = (t < sm_len[b]) ? dot * sm_inv[b] * expf(ev) : qlast;
            qlast = qn;
            __stcg(&qcur[(size_t)jbase * 16 + tid], qn);
        }
    }

    // ---------------- final: logprob_b = C_b + log( sum_j q_T[b,j]*exp(final_j) )
    __syncthreads();
    if (tid < NOUT) red[tid] = qlast * expf(__ldg(&finalv[jg]));
    __syncthreads();
    if (tid < 16) {
        float p = 0.f;
        #pragma unroll
        for (int c = 0; c < JT; c++) p += red[c * 16 + tid];
        g_part[blockIdx.x][tid] = p;
    }
    __threadfence();
    grid_barrier();
    if (tracker && tid < 16) {
        double tot = 0.0;
        for (int c = 0; c < nCtaProb; c++)
            tot += (double)__ldcg(&g_part[ctaFirst + c][tid]);
        g_lp[PROB][tid] = Creg + log(tot);
    }
    __threadfence();
    grid_barrier();
}

// -------------------- kernel ------------------------------------------------
__global__ void __launch_bounds__(NTHR, 1)
lfmmi_kernel(const float* input, const int* seqlen,
             const float* n_init, const float* n_trans, const float* n_final, const int* n_pdf,
             const float* d_init, const float* d_trans, const float* d_final, const int* d_pdf,
             float* out)
{
    int cta = blockIdx.x;
    if (cta < NC_DEN) {
        run_fsm<SD, 8, 0>(input, seqlen, d_init, d_trans, d_final, d_pdf,
                          g_qden[0], g_qden[1], cta, cta == 0, 0, NC_DEN);
    } else {
        run_fsm<SN, 32, 1>(input, seqlen, n_init, n_trans, n_final, n_pdf,
                           g_qnum[0], g_qnum[1], cta - NC_DEN, cta == NC_DEN,
                           NC_DEN, NC_NUM);
    }
    if (cta == 0 && threadIdx.x == 0) {
        double dsum = 0.0, nsum = 0.0;
        for (int bb = 0; bb < 16; ++bb) {
            dsum += __ldcg(&g_lp[0][bb]);
            nsum += __ldcg(&g_lp[1][bb]);
        }
        out[0] = (float)(-(nsum - dsum));
    }
}

// -------------------- launch -------------------------------------------------
extern "C" void kernel_launch(void* const* d_in, const int* in_sizes, int n_in,
                              void* d_out, int out_size)
{
    (void)in_sizes; (void)n_in; (void)out_size;
    // floats: Es 8192 + qs 16384 + red 10240 + sswarp 256 + inv 16 + len 16
    const size_t smem = (8192 + 16384 + 10240 + 256 + 16 + 16) * sizeof(float);
    cudaFuncSetAttribute(lfmmi_kernel,
                         cudaFuncAttributeMaxDynamicSharedMemorySize, (int)smem);
    lfmmi_kernel<<<NCTA, NTHR, smem>>>(
        (const float*)d_in[0], (const int*)d_in[1],
        (const float*)d_in[2], (const float*)d_in[3], (const float*)d_in[4], (const int*)d_in[5],
        (const float*)d_in[6], (const float*)d_in[7], (const float*)d_in[8], (const int*)d_in[9],
        (float*)d_out);
}

// round 13
// speedup vs baseline: 1.4587x; 1.0255x over previous
#include <cuda_runtime.h>
#include <cstdint>
#include <math.h>

#define B_   16
#define T_   512
#define P_   2048
#define SN   256
#define SD   1024
#define NC_DEN 128
#define NC_NUM 8
#define NCTA (NC_DEN + NC_NUM)
#define NTHR 512

// -------------------- persistent device scratch (no runtime allocation) -----
__device__ float g_qden[2][SD * 16];
__device__ float g_qnum[2][SN * 16];
__device__ float g_part[NCTA][16];
__device__ double g_lp[2][16];
__device__ unsigned long long g_bar;   // monotonic; survives graph replays

__device__ __forceinline__ unsigned long long ld_relaxed_u64(const unsigned long long* p) {
    unsigned long long v;
    asm volatile("ld.relaxed.gpu.u64 %0, [%1];" : "=l"(v) : "l"(p));
    return v;
}

// -------------------- grid barrier (136 CTAs co-resident) -------------------
__device__ __forceinline__ void grid_barrier() {
    __syncthreads();                       // all CTA threads done with prior step
    if (threadIdx.x == 0) {
        __threadfence();                   // cumulative release
        unsigned long long old = atomicAdd(&g_bar, 1ULL);
        unsigned long long target = (old / NCTA + 1ULL) * (unsigned long long)NCTA;
        while (ld_relaxed_u64(&g_bar) < target) { }
        __threadfence();                   // acquire
    }
    __syncthreads();
}

__device__ __forceinline__ void f4fma(float4& a, const float4& q, float e) {
    a.x = fmaf(q.x, e, a.x);
    a.y = fmaf(q.y, e, a.y);
    a.z = fmaf(q.z, e, a.z);
    a.w = fmaf(q.w, e, a.w);
}

// -------------------- one FSM (num or den), one column tile per CTA ---------
// q layout in global: q[i*16 + b]  (b contiguous)
template <int S, int JT, int PROB>
__device__ void run_fsm(const float* __restrict__ input,
                        const int*   __restrict__ seqlen,
                        const float* __restrict__ initv,
                        const float* __restrict__ trans,
                        const float* __restrict__ finalv,
                        const int*   __restrict__ pdf,
                        float* q0buf, float* q1buf,
                        int tileIdx, bool tracker, int ctaFirst, int nCtaProb)
{
    constexpr int JQ   = JT / 4;            // den: 2,  num: 8
    constexpr int GRP  = 4 * JQ;            // den: 8,  num: 32
    constexpr int NSEG = NTHR / GRP;        // den: 64, num: 16
    constexpr int ILEN = S / NSEG;          // 16 (both)
    constexpr int NOUT = 16 * JT;           // den: 128, num: 512
    constexpr int ROWP = NOUT + 32;         // padded red row
    constexpr int NLD  = S / 128;           // per-thread float4 stage loads (den 8, num 2)
    constexpr int WQ4  = S / 4;             // q4 slots staged per warp

    const int tid   = threadIdx.x;
    const int lane  = tid & 31;
    const int warp  = tid >> 5;
    const int jbase = tileIdx * JT;

    extern __shared__ float sm[];
    float* Es     = sm;                       // 8192 floats (S*JT = 8192 both)
    float* qs     = sm + 8192;                // up to 16384 floats (S*16)
    float* red    = qs + 16384;               // up to 10240 floats (NSEG*ROWP)
    float* sswarp = red + 10240;              // 256 floats (16 warps x 16 b)
    int*   sm_len = (int*)(sswarp + 256);     // 16 ints

    if (tid < 16) sm_len[tid] = seqlen[tid];

    // E tile resident in SMEM: Es[i*JT + jl] = exp(trans[i][jbase+jl])
    for (int k = tid; k < S * JT; k += NTHR) {
        int i = k / JT, jl = k % JT;
        Es[k] = expf(__ldg(&trans[(size_t)i * S + jbase + jl]));
    }

    // output-thread mapping: tid -> (b = tid%16, j = tid/16)
    int b = 0, jg = 0, pdfj = 0;
    float qlast = 0.f;
    if (tid < NOUT) {
        b  = tid & 15;
        jg = jbase + (tid >> 4);
        pdfj = __ldg(&pdf[jg]);
        qlast = expf(__ldg(&initv[jg]) + __ldg(&input[(size_t)b * T_ * P_ + pdfj]));
        __stcg(&q0buf[(size_t)jbase * 16 + tid], qlast);
    }

    double Creg = 0.0;                        // tracker-only running log-offset

    // GEMM thread coords: 4b x 4j register tile; warp w consumes i in [ILEN*GRPseg...]
    const int jq   = tid % JQ;
    const int bq   = (tid / JQ) & 3;
    const int iseg = tid / GRP;
    const int i0   = iseg * ILEN;
    float* wrbase = red + iseg * ROWP + bq * (4 * JT) + jq * 4 + bq * 8;
    const int ridx = b * JT + (tid >> 4) + (b >> 2) * 8;

    for (int t = 1; t < T_; ++t) {
        // prefetch this step's emission BEFORE the barrier (depends only on t)
        float ev = 0.f;
        if (tid < NOUT) ev = __ldg(&input[((size_t)b * T_ + t) * P_ + pdfj]);

        grid_barrier();                       // q(t-1) globally visible
        const float* qprev = (t & 1) ? q0buf : q1buf;
        float*       qcur  = (t & 1) ? q1buf : q0buf;

        // warp-local stage: warp w stages exactly its own GEMM i-slice,
        // fusing the per-b partial sum
        float4 ps = make_float4(0.f, 0.f, 0.f, 0.f);
        {
            const float4* src = (const float4*)qprev;
            float4*       dst = (float4*)qs;
            #pragma unroll
            for (int u = 0; u < NLD; u++) {
                int k = warp * WQ4 + u * 32 + lane;
                float4 v = __ldcg(src + k);
                dst[k] = v;
                ps.x += v.x; ps.y += v.y; ps.z += v.z; ps.w += v.w;
            }
        }
        // butterfly over lanes with same lane%4 (b-quad preserved)
        #pragma unroll
        for (int m = 4; m < 32; m <<= 1) {
            ps.x += __shfl_xor_sync(0xffffffffu, ps.x, m);
            ps.y += __shfl_xor_sync(0xffffffffu, ps.y, m);
            ps.z += __shfl_xor_sync(0xffffffffu, ps.z, m);
            ps.w += __shfl_xor_sync(0xffffffffu, ps.w, m);
        }
        if (lane < 4) ((float4*)sswarp)[warp * 4 + lane] = ps;   // sswarp[warp][b]
        __syncwarp();

        // GEMM slice: 16 accumulators (4 j x 4 b), ILEN=16 i's, warp-local qs
        float4 a0 = make_float4(0,0,0,0), a1 = a0, a2 = a0, a3 = a0;
        {
            const float4* q4 = (const float4*)qs;
            const float4* E4 = (const float4*)Es;
            #pragma unroll
            for (int ii = 0; ii < ILEN; ii++) {
                int i = i0 + ii;
                float4 qv = q4[i * 4 + bq];
                float4 e4 = E4[i * JQ + jq];
                f4fma(a0, qv, e4.x);
                f4fma(a1, qv, e4.y);
                f4fma(a2, qv, e4.z);
                f4fma(a3, qv, e4.w);
            }
        }
        // transpose 4x4 and store float4-over-j into red
        {
            *(float4*)(wrbase + 0 * JT) = make_float4(a0.x, a1.x, a2.x, a3.x);
            *(float4*)(wrbase + 1 * JT) = make_float4(a0.y, a1.y, a2.y, a3.y);
            *(float4*)(wrbase + 2 * JT) = make_float4(a0.z, a1.z, a2.z, a3.z);
            *(float4*)(wrbase + 3 * JT) = make_float4(a0.w, a1.w, a2.w, a3.w);
        }
        __syncthreads();                      // the ONE block-wide sync per step

        // q(t)[b,j] = dot / s_b * exp(emis); frozen b carries forward
        if (tid < NOUT) {
            float dot = 0.f;
            #pragma unroll
            for (int s2 = 0; s2 < NSEG; s2++) dot += red[s2 * ROWP + ridx];
            float s = 0.f;
            #pragma unroll
            for (int w = 0; w < 16; w++) s += sswarp[w * 16 + b];
            float qn = (t < sm_len[b]) ? (dot / s) * expf(ev) : qlast;
            qlast = qn;
            __stcg(&qcur[(size_t)jbase * 16 + tid], qn);
            if (tracker && tid < 16 && t < sm_len[b]) Creg += (double)logf(s);
        }
    }

    // ---------------- final: logprob_b = C_b + log( sum_j q_T[b,j]*exp(final_j) )
    __syncthreads();
    if (tid < NOUT) red[tid] = qlast * expf(__ldg(&finalv[jg]));
    __syncthreads();
    if (tid < 16) {
        float p = 0.f;
        #pragma unroll
        for (int c = 0; c < JT; c++) p += red[c * 16 + tid];
        g_part[blockIdx.x][tid] = p;
    }
    __threadfence();
    grid_barrier();
    if (tracker && tid < 16) {
        double tot = 0.0;
        for (int c = 0; c < nCtaProb; c++)
            tot += (double)__ldcg(&g_part[ctaFirst + c][tid]);
        g_lp[PROB][tid] = Creg + log(tot);
    }
    __threadfence();
    grid_barrier();
}

// -------------------- kernel ------------------------------------------------
__global__ void __launch_bounds__(NTHR, 1)
lfmmi_kernel(const float* input, const int* seqlen,
             const float* n_init, const float* n_trans, const float* n_final, const int* n_pdf,
             const float* d_init, const float* d_trans, const float* d_final, const int* d_pdf,
             float* out)
{
    int cta = blockIdx.x;
    if (cta < NC_DEN) {
        run_fsm<SD, 8, 0>(input, seqlen, d_init, d_trans, d_final, d_pdf,
                          g_qden[0], g_qden[1], cta, cta == 0, 0, NC_DEN);
    } else {
        run_fsm<SN, 32, 1>(input, seqlen, n_init, n_trans, n_final, n_pdf,
                           g_qnum[0], g_qnum[1], cta - NC_DEN, cta == NC_DEN,
                           NC_DEN, NC_NUM);
    }
    if (cta == 0 && threadIdx.x == 0) {
        double dsum = 0.0, nsum = 0.0;
        for (int bb = 0; bb < 16; ++bb) {
            dsum += __ldcg(&g_lp[0][bb]);
            nsum += __ldcg(&g_lp[1][bb]);
        }
        out[0] = (float)(-(nsum - dsum));
    }
}

// -------------------- launch -------------------------------------------------
extern "C" void kernel_launch(void* const* d_in, const int* in_sizes, int n_in,
                              void* d_out, int out_size)
{
    (void)in_sizes; (void)n_in; (void)out_size;
    // floats: Es 8192 + qs 16384 + red 10240 + sswarp 256 + len 16
    const size_t smem = (8192 + 16384 + 10240 + 256 + 16) * sizeof(float);
    cudaFuncSetAttribute(lfmmi_kernel,
                         cudaFuncAttributeMaxDynamicSharedMemorySize, (int)smem);
    lfmmi_kernel<<<NCTA, NTHR, smem>>>(
        (const float*)d_in[0], (const int*)d_in[1],
        (const float*)d_in[2], (const float*)d_in[3], (const float*)d_in[4], (const int*)d_in[5],
        (const float*)d_in[6], (const float*)d_in[7], (const float*)d_in[8], (const int*)d_in[9],
        (float*)d_out);
}